// round 3
// baseline (speedup 1.0000x reference)
#include <cuda_runtime.h>

// EmbeddingBlock: out = swish( [emb[z[s]] | emb[z[d]] | e_rbf@edge_W^T] @ dense_W^T + b )
//
// Factorization (VOCAB=100 distinct embedding rows):
//   P12[vs][vd] = emb[vs]@W[:, :128]^T + emb[vd]@W[:,128:256]^T + b  (100^2 x 272, 10.9 MB, L2-resident)
//   W3eff       = edge_W^T @ W[:,256:272]^T                          (16 x 272, register-resident)
// Per edge: out = swish( P12[pair[e]] + e_rbf[e] @ W3eff )  -> memory-bound epilogue.
// R3: 4 edges in flight per thread (MLP 4) to cover L2 latency.

#define D    128
#define RBF  16
#define CAT  272
#define J4   68
#define VMAX 128
#define EMAX 1048576

__device__ float4 g_W3[RBF * J4];
__device__ float  g_P1[VMAX * CAT];
__device__ float  g_P2[VMAX * CAT];
__device__ float4 g_P12[VMAX * VMAX * J4];
__device__ int    g_pair[EMAX];              // pair index premultiplied by J4

// ---------------------------------------------------------------------------
__global__ void prep_tables(const float* __restrict__ emb,
                            const float* __restrict__ dW,
                            const float* __restrict__ eW,
                            int V) {
    const int bid = blockIdx.x;
    const int j   = threadIdx.x;          // 0..271
    if (bid < V) {
        __shared__ float sh_emb[D];
        if (j < D) sh_emb[j] = emb[bid * D + j];
        __syncthreads();
        const float4* wrow = reinterpret_cast<const float4*>(dW + (long long)j * CAT);
        float a1 = 0.f, a2 = 0.f;
#pragma unroll
        for (int k4 = 0; k4 < D / 4; ++k4) {
            float4 t = wrow[k4];
            a1 = fmaf(sh_emb[4 * k4 + 0], t.x, a1);
            a1 = fmaf(sh_emb[4 * k4 + 1], t.y, a1);
            a1 = fmaf(sh_emb[4 * k4 + 2], t.z, a1);
            a1 = fmaf(sh_emb[4 * k4 + 3], t.w, a1);
        }
#pragma unroll
        for (int k4 = 0; k4 < D / 4; ++k4) {
            float4 t = wrow[D / 4 + k4];
            a2 = fmaf(sh_emb[4 * k4 + 0], t.x, a2);
            a2 = fmaf(sh_emb[4 * k4 + 1], t.y, a2);
            a2 = fmaf(sh_emb[4 * k4 + 2], t.z, a2);
            a2 = fmaf(sh_emb[4 * k4 + 3], t.w, a2);
        }
        g_P1[bid * CAT + j] = a1;
        g_P2[bid * CAT + j] = a2;
    } else {
        const int r = bid - V;
        float a = 0.f;
#pragma unroll
        for (int i = 0; i < RBF; ++i)
            a = fmaf(eW[i * RBF + r], dW[(long long)j * CAT + 2 * D + i], a);
        reinterpret_cast<float*>(g_W3)[r * CAT + j] = a;
    }
}

// ---------------------------------------------------------------------------
__global__ void prep_pairs(const float* __restrict__ b, int V) {
    const int bid = blockIdx.x;
    const int vs  = bid / V;
    const int vd  = bid - vs * V;
    const int j   = threadIdx.x;
    float val = g_P1[vs * CAT + j] + g_P2[vd * CAT + j] + b[j];
    reinterpret_cast<float*>(g_P12)[(long long)bid * CAT + j] = val;
}

// ---------------------------------------------------------------------------
__global__ void prep_pair_idx(const int* __restrict__ z,
                              const int* __restrict__ nbr,
                              int E, int V) {
    int e = blockIdx.x * blockDim.x + threadIdx.x;
    if (e < E) {
        int2 nn = reinterpret_cast<const int2*>(nbr)[e];
        g_pair[e] = (__ldg(&z[nn.x]) * V + __ldg(&z[nn.y])) * J4;
    }
}

// ---------------------------------------------------------------------------
// Per-edge epilogue tail: e_rbf @ W3 + swish + store
__device__ __forceinline__ void finish_edge(const float4* __restrict__ e4,
                                            float4* __restrict__ out4,
                                            const float4 (&w)[RBF],
                                            float4 acc, int e, int tx, bool valid,
                                            int E) {
    long long eb = (long long)(valid ? e : (E - 1)) * 4;
    float4 a0 = __ldg(&e4[eb + 0]);
    float4 a1 = __ldg(&e4[eb + 1]);
    float4 a2 = __ldg(&e4[eb + 2]);
    float4 a3 = __ldg(&e4[eb + 3]);
    const float er[RBF] = {a0.x, a0.y, a0.z, a0.w, a1.x, a1.y, a1.z, a1.w,
                           a2.x, a2.y, a2.z, a2.w, a3.x, a3.y, a3.z, a3.w};
#pragma unroll
    for (int r = 0; r < RBF; ++r) {
        acc.x = fmaf(er[r], w[r].x, acc.x);
        acc.y = fmaf(er[r], w[r].y, acc.y);
        acc.z = fmaf(er[r], w[r].z, acc.z);
        acc.w = fmaf(er[r], w[r].w, acc.w);
    }
    acc.x = acc.x / (1.f + __expf(-acc.x));
    acc.y = acc.y / (1.f + __expf(-acc.y));
    acc.z = acc.z / (1.f + __expf(-acc.z));
    acc.w = acc.w / (1.f + __expf(-acc.w));
    if (valid) __stcs(&out4[(long long)e * J4 + tx], acc);
}

// ---------------------------------------------------------------------------
// Hot kernel. block = (68, 4). 4 edges per thread per iteration -> 4 P12
// float4 loads in flight per lane. Pair indices prefetched one iter ahead.
__global__ void __launch_bounds__(272, 2)
edge_main(const float4* __restrict__ e4, float4* __restrict__ out4, int E) {
    const int tx = threadIdx.x;            // 0..67
    const int ty = threadIdx.y;            // 0..3

    float4 w[RBF];
#pragma unroll
    for (int r = 0; r < RBF; ++r) w[r] = g_W3[r * J4 + tx];

    const int stride = gridDim.x * 16;
    int base = blockIdx.x * 16;
    if (base >= E) return;

    int e0 = base + ty, e1 = e0 + 4, e2 = e0 + 8, e3 = e0 + 12;
    int p0 = (e0 < E) ? __ldg(&g_pair[e0]) : 0;
    int p1 = (e1 < E) ? __ldg(&g_pair[e1]) : 0;
    int p2 = (e2 < E) ? __ldg(&g_pair[e2]) : 0;
    int p3 = (e3 < E) ? __ldg(&g_pair[e3]) : 0;

    for (; base < E; base += stride) {
        const bool v0 = (e0 < E), v1 = (e1 < E), v2 = (e2 < E), v3 = (e3 < E);

        // ---- issue all four P12 row loads (L2) back-to-back ----
        float4 acc0 = g_P12[p0 + tx];
        float4 acc1 = g_P12[(v1 ? p1 : 0) + tx];
        float4 acc2 = g_P12[(v2 ? p2 : 0) + tx];
        float4 acc3 = g_P12[(v3 ? p3 : 0) + tx];

        // ---- prefetch next iteration's pair indices ----
        int ne0 = e0 + stride, ne1 = e1 + stride, ne2 = e2 + stride, ne3 = e3 + stride;
        int np0 = (ne0 < E) ? __ldg(&g_pair[ne0]) : 0;
        int np1 = (ne1 < E) ? __ldg(&g_pair[ne1]) : 0;
        int np2 = (ne2 < E) ? __ldg(&g_pair[ne2]) : 0;
        int np3 = (ne3 < E) ? __ldg(&g_pair[ne3]) : 0;

        finish_edge(e4, out4, w, acc0, e0, tx, v0, E);
        finish_edge(e4, out4, w, acc1, e1, tx, v1, E);
        finish_edge(e4, out4, w, acc2, e2, tx, v2, E);
        finish_edge(e4, out4, w, acc3, e3, tx, v3, E);

        e0 = ne0; e1 = ne1; e2 = ne2; e3 = ne3;
        p0 = np0; p1 = np1; p2 = np2; p3 = np3;
    }
}

// ---------------------------------------------------------------------------
extern "C" void kernel_launch(void* const* d_in, const int* in_sizes, int n_in,
                              void* d_out, int out_size) {
    const float* e_rbf  = (const float*)d_in[0];
    const int*   z      = (const int*)  d_in[1];
    const int*   nbr    = (const int*)  d_in[2];
    const float* edge_W = (const float*)d_in[3];
    const float* emb    = (const float*)d_in[4];
    const float* dW     = (const float*)d_in[5];
    const float* db     = (const float*)d_in[6];
    float* out = (float*)d_out;

    const int E = in_sizes[0] / RBF;     // 800000
    const int V = in_sizes[4] / D;       // 100

    prep_tables<<<V + RBF, CAT>>>(emb, dW, edge_W, V);
    prep_pairs<<<V * V, CAT>>>(db, V);
    prep_pair_idx<<<(E + 255) / 256, 256>>>(z, nbr, E, V);

    dim3 blk(J4, 4);
    edge_main<<<296, blk>>>(reinterpret_cast<const float4*>(e_rbf),
                            reinterpret_cast<float4*>(out), E);
}